// round 5
// baseline (speedup 1.0000x reference)
#include <cuda_runtime.h>

// CRF forward recursion — multiplicative exp2-domain, column-split over 2 warps.
// Batch = 2 warps (64 threads). Lane owns ONE nxt-column c = 32*w2 + lane and
// performs the full 64-long prev reduction in-lane with packed fp32x2 FMAs
// (its E column resident in 32 packed registers). p = exp2(alpha - M) is
// exchanged via smem: one 32-float STS per warp + ONE 64-thread named barrier
// per timestep. The scale shift d = lg2(p'[2]) and u = exp2(x*log2e - d) are
// computed after the barrier, hidden under the next step's matvec.
// CTA = 128 threads = 2 independent batches (separate named barriers).

#define FULLMASK 0xffffffffu
typedef unsigned long long ull;

__device__ __forceinline__ float ex2f_(float x){float r;asm("ex2.approx.f32 %0,%1;":"=f"(r):"f"(x));return r;}
__device__ __forceinline__ float lg2f_(float x){float r;asm("lg2.approx.f32 %0,%1;":"=f"(r):"f"(x));return r;}
__device__ __forceinline__ ull  pack2_(float lo,float hi){ull r;asm("mov.b64 %0,{%1,%2};":"=l"(r):"f"(lo),"f"(hi));return r;}
__device__ __forceinline__ void unpack2_(ull v,float&a,float&b){asm("mov.b64 {%0,%1},%2;":"=f"(a),"=f"(b):"l"(v));}
__device__ __forceinline__ ull ffma2_(ull a,ull b,ull c){ull d;asm("fma.rn.f32x2 %0,%1,%2,%3;":"=l"(d):"l"(a),"l"(b),"l"(c));return d;}
__device__ __forceinline__ ull fadd2_(ull a,ull b){ull d;asm("add.rn.f32x2 %0,%1,%2;":"=l"(d):"l"(a),"l"(b));return d;}

__global__ __launch_bounds__(128, 1)
void crf_forward_kernel(const float* __restrict__ X,
                        const float* __restrict__ trans,
                        float* __restrict__ out,
                        int B, int T)
{
    constexpr float LOG2E = 1.4426950408889634f;
    constexpr float LN2   = 0.6931471805599453f;
    constexpr float NEG2  = -10000.0f * 1.4426950408889634f;

    const int tid  = threadIdx.x;
    const int g    = tid >> 6;                 // batch slot in CTA (0/1)
    const int w2   = (tid >> 5) & 1;           // warp within batch
    const int lane = tid & 31;
    const int c    = (w2 << 5) | lane;         // owned column (0..63)

    int b = blockIdx.x * 2 + g;
    if (b >= B) b = 0;                         // defensive (B even here)

    // p exchange: [batch][double-buffer][64 floats]
    __shared__ __align__(16) float pbuf[2][2][64];

    // ---- E column in registers: e[k] = (E2[2k][c], E2[2k+1][c]).
    // Column 0 (tag 'B', trans masked to -1e4) overridden to 1.0; the -1e4
    // is applied exactly via u(0)=0 in the mainloop and the NEG2 constant in
    // the epilogue. Row 1 (tag 'E') underflows to exactly 0 — matches ref.
    ull e[32];
#pragma unroll
    for (int k = 0; k < 32; k++) {
        const float t0 = __ldg(&trans[(2 * k    ) * 64 + c]);
        const float t1 = __ldg(&trans[(2 * k + 1) * 64 + c]);
        const float f0 = (c == 0) ? 1.0f : ex2f_(t0 * LOG2E);
        const float f1 = (c == 0) ? 1.0f : ex2f_(t1 * LOG2E);
        e[k] = pack2_(f0, f1);
    }

    // ---- init p_0 = (1, 0, ..., 0)
    pbuf[g][0][c] = (c == 0) ? 1.0f : 0.0f;

    const float* __restrict__ xp = X + (size_t)b * T * 64 + c;

    // u_0 = exp2(x_0 * log2e) (d_0 = 0), masked at column 0
    float u = (c == 0) ? 0.0f : ex2f_(xp[0] * LOG2E);
    float xnext = xp[(size_t)((T > 1) ? 1 : 0) * 64];   // x_1
    float M = 0.0f, du = 0.0f;

    const int barid = 1 + g;
    asm volatile("bar.sync %0, 64;" :: "r"(barid) : "memory");

    int cur = 0;

    for (int t = 0; t < T - 1; t++) {
        // ---- full matvec for own column: S = sum_prev p[prev] * E2[prev][c]
        const ulonglong2* __restrict__ pp = (const ulonglong2*)pbuf[g][cur];
        ull a0 = 0, a1 = 0, a2 = 0, a3 = 0;
#pragma unroll
        for (int k = 0; k < 8; k++) {
            const ulonglong2 pv0 = pp[2 * k];       // prevs 8k..8k+3
            const ulonglong2 pv1 = pp[2 * k + 1];   // prevs 8k+4..8k+7
            a0 = ffma2_(pv0.x, e[4 * k + 0], a0);
            a1 = ffma2_(pv0.y, e[4 * k + 1], a1);
            a2 = ffma2_(pv1.x, e[4 * k + 2], a2);
            a3 = ffma2_(pv1.y, e[4 * k + 3], a3);
        }
        const ull sp = fadd2_(fadd2_(a0, a1), fadd2_(a2, a3));
        float sa, sb;
        unpack2_(sp, sa, sb);
        const float S = sa + sb;

        // ---- scale, publish, sync (critical path)
        pbuf[g][cur ^ 1][c] = S * u;
        asm volatile("bar.sync %0, 64;" :: "r"(barid) : "memory");

        // ---- shadow work: next shift + next u (consumed after next matvec)
        const float dn = lg2f_(pbuf[g][cur ^ 1][2]);   // broadcast LDS
        M += du;
        du = dn;
        float un = ex2f_(fmaf(xnext, LOG2E, -dn));
        if (c == 0) un = 0.0f;
        u = un;

        int t2 = t + 2; if (t2 > T - 1) t2 = T - 1;
        xnext = xp[(size_t)t2 * 64];

        cur ^= 1;
    }

    // ---- epilogue: final matvec + x_{T-1}; reconstruct natural-log alpha.
    {
        const ulonglong2* __restrict__ pp = (const ulonglong2*)pbuf[g][cur];
        ull a0 = 0, a1 = 0, a2 = 0, a3 = 0;
#pragma unroll
        for (int k = 0; k < 8; k++) {
            const ulonglong2 pv0 = pp[2 * k];
            const ulonglong2 pv1 = pp[2 * k + 1];
            a0 = ffma2_(pv0.x, e[4 * k + 0], a0);
            a1 = ffma2_(pv0.y, e[4 * k + 1], a1);
            a2 = ffma2_(pv1.x, e[4 * k + 2], a2);
            a3 = ffma2_(pv1.y, e[4 * k + 3], a3);
        }
        const ull sp = fadd2_(fadd2_(a0, a1), fadd2_(a2, a3));
        float sa, sb;
        unpack2_(sp, sa, sb);
        const float S = sa + sb;

        const float mask = (c == 0) ? NEG2 : 0.0f;
        out[(size_t)b * 64 + c] =
            (lg2f_(S) + xnext * LOG2E + mask + M) * LN2;  // xnext == x_{T-1}
    }
}

extern "C" void kernel_launch(void* const* d_in, const int* in_sizes, int n_in,
                              void* d_out, int out_size)
{
    const float* X     = (const float*)d_in[0];
    const float* trans = (const float*)d_in[1];
    float* out = (float*)d_out;

    const int B = out_size / 64;               // 256
    const int T = in_sizes[0] / (B * 64);      // 512

    const int blocks = (B + 1) / 2;            // 2 batches (4 warps) per CTA
    crf_forward_kernel<<<blocks, 128>>>(X, trans, out, B, T);
}

// round 6
// speedup vs baseline: 1.1569x; 1.1569x over previous
#include <cuda_runtime.h>

// CRF forward recursion — multiplicative exp2-domain, one WARP per batch.
// Each lane owns columns (2*lane, 2*lane+1); full 64-prev reduction with
// packed fp32x2 FMAs (E2 resident in 128 registers); p exchanged via
// warp-private double-buffered smem with ONE __syncwarp per step.
// ROTATED schedule: STS(pn) -> syncwarp happens immediately; the renorm/u
// side chain (SHFL p[2] -> lg2 -> ex2) issues AFTER the sync, hidden in the
// next matvec's LDS-latency window. Loop unrolled x2 over the ping-pong.

#define FULLMASK 0xffffffffu
typedef unsigned long long ull;

__device__ __forceinline__ float ex2f_(float x){float r;asm("ex2.approx.f32 %0,%1;":"=f"(r):"f"(x));return r;}
__device__ __forceinline__ float lg2f_(float x){float r;asm("lg2.approx.f32 %0,%1;":"=f"(r):"f"(x));return r;}
__device__ __forceinline__ ull  pack2_(float lo,float hi){ull r;asm("mov.b64 %0,{%1,%2};":"=l"(r):"f"(lo),"f"(hi));return r;}
__device__ __forceinline__ void unpack2_(ull v,float&a,float&b){asm("mov.b64 {%0,%1},%2;":"=f"(a),"=f"(b):"l"(v));}
__device__ __forceinline__ float lo2_(ull v){float a,b;unpack2_(v,a,b);return a;}
__device__ __forceinline__ ull ffma2_(ull a,ull b,ull c){ull d;asm("fma.rn.f32x2 %0,%1,%2,%3;":"=l"(d):"l"(a),"l"(b),"l"(c));return d;}
__device__ __forceinline__ ull fadd2_(ull a,ull b){ull d;asm("add.rn.f32x2 %0,%1,%2;":"=l"(d):"l"(a),"l"(b));return d;}
__device__ __forceinline__ ull fmul2_(ull a,ull b){ull d;asm("mul.rn.f32x2 %0,%1,%2;":"=l"(d):"l"(a),"l"(b));return d;}

// Matvec over all 64 prevs for this lane's 2 columns; PTRP = smem p buffer.
#define MATVEC_BODY(PTRP)                                              \
    {                                                                  \
        const ulonglong2* __restrict__ pp = (const ulonglong2*)(PTRP); \
        ull A0=0,A1=0,A2=0,A3=0,B0=0,B1=0,B2=0,B3=0;                   \
        _Pragma("unroll")                                              \
        for (int k = 0; k < 8; k++) {                                  \
            const ulonglong2 pv0 = pp[2*k];                            \
            const ulonglong2 pv1 = pp[2*k+1];                          \
            A0 = ffma2_(pv0.x, e0[4*k+0], A0);                         \
            B0 = ffma2_(pv0.x, e1[4*k+0], B0);                         \
            A1 = ffma2_(pv0.y, e0[4*k+1], A1);                         \
            B1 = ffma2_(pv0.y, e1[4*k+1], B1);                         \
            A2 = ffma2_(pv1.x, e0[4*k+2], A2);                         \
            B2 = ffma2_(pv1.x, e1[4*k+2], B2);                         \
            A3 = ffma2_(pv1.y, e0[4*k+3], A3);                         \
            B3 = ffma2_(pv1.y, e1[4*k+3], B3);                         \
        }                                                              \
        const ull sa = fadd2_(fadd2_(A0,A1), fadd2_(A2,A3));           \
        const ull sb = fadd2_(fadd2_(B0,B1), fadd2_(B2,B3));           \
        float sa0,sa1,sb0,sb1;                                         \
        unpack2_(sa,sa0,sa1); unpack2_(sb,sb0,sb1);                    \
        S0 = sa0+sa1; S1 = sb0+sb1;                                    \
    }

// One mainloop step t>=1: prep u_t from pn (=p_t) + xq0 (=x_t), matvec from
// pbuf[BUF], produce p_{t+1}, publish, sync.
#define STEP(BUF)                                                      \
    {                                                                  \
        const float p2 = __shfl_sync(FULLMASK, lo2_(pn), 1);           \
        const float dn = lg2f_(p2);                                    \
        M += dn;                                                       \
        float un0 = ex2f_(fmaf(xq0.x, LOG2E, -dn));                    \
        float un1 = ex2f_(fmaf(xq0.y, LOG2E, -dn));                    \
        if (c0 == 0) un0 = 0.0f;                                       \
        const ull u = pack2_(un0, un1);                                \
        xq0 = xq1;                                                     \
        xq1 = *(const float2*)xpre;                                    \
        xpre += 64; if (xpre > xlast) xpre = xlast;                    \
        float S0, S1;                                                  \
        MATVEC_BODY(pbuf[w][BUF]);                                     \
        pn = fmul2_(pack2_(S0, S1), u);                                \
        *(ull*)&pbuf[w][(BUF) ^ 1][c0] = pn;                           \
        __syncwarp();                                                  \
    }

__global__ __launch_bounds__(64, 1)
void crf_forward_kernel(const float* __restrict__ X,
                        const float* __restrict__ trans,
                        float* __restrict__ out,
                        int B, int T)
{
    constexpr float LOG2E = 1.4426950408889634f;
    constexpr float LN2   = 0.6931471805599453f;
    constexpr float NEG2  = -10000.0f * 1.4426950408889634f;

    const int tid  = threadIdx.x;
    const int w    = tid >> 5;
    const int lane = tid & 31;
    const int c0   = 2 * lane;
    const int c1   = c0 + 1;
    int b = blockIdx.x * 2 + w;
    if (b >= B) b = 0;                         // defensive (B even here)

    __shared__ __align__(16) float pbuf[2][2][64];

    // E2 = exp2(trans*log2e) packed over prev pairs: e0[k]=(E[2k][c0],E[2k+1][c0]).
    // Column 0 (tag 'B', masked -1e4) overridden to 1.0; the -1e4 is applied
    // exactly via u[0]=0 per step and NEG2 in the epilogue. Row 1 (tag 'E')
    // underflows to exactly 0 — matches reference.
    ull e0[32], e1[32];
#pragma unroll
    for (int k = 0; k < 32; k++) {
        const float t00 = trans[(2*k    ) * 64 + c0];
        const float t10 = trans[(2*k + 1) * 64 + c0];
        const float t01 = trans[(2*k    ) * 64 + c1];
        const float t11 = trans[(2*k + 1) * 64 + c1];
        e0[k] = pack2_((c0 == 0) ? 1.0f : ex2f_(t00 * LOG2E),
                       (c0 == 0) ? 1.0f : ex2f_(t10 * LOG2E));
        e1[k] = pack2_(ex2f_(t01 * LOG2E), ex2f_(t11 * LOG2E));
    }

    // init p_0 = (1, 0, ..., 0)
    *(ull*)&pbuf[w][0][c0] = pack2_((c0 == 0) ? 1.0f : 0.0f, 0.0f);

    const float* __restrict__ xp = X + (size_t)b * T * 64 + c0;
    const float* xlast = xp + (size_t)(T - 1) * 64;

    // u_0 = exp2(x_0*log2e), d_0 = 0, masked at column 0
    const float2 x0v = *(const float2*)xp;
    const ull u0 = pack2_((c0 == 0) ? 0.0f : ex2f_(x0v.x * LOG2E),
                          ex2f_(x0v.y * LOG2E));

    // x prefetch queue: xq0 = x_1, xq1 = x_2 (clamped for tiny T)
    const float* x1p = xp + 64;  if (x1p > xlast) x1p = xlast;
    const float* x2p = xp + 128; if (x2p > xlast) x2p = xlast;
    float2 xq0 = *(const float2*)x1p;
    float2 xq1 = *(const float2*)x2p;
    const float* xpre = xp + 192; if (xpre > xlast) xpre = xlast;

    float M = 0.0f;
    ull pn;
    __syncwarp();

    // ---- peeled body 0: p_1 = (p_0 E) * u_0   (no shift)
    {
        float S0, S1;
        MATVEC_BODY(pbuf[w][0]);
        pn = fmul2_(pack2_(S0, S1), u0);
        *(ull*)&pbuf[w][1][c0] = pn;
        __syncwarp();
    }

    // ---- bodies t = 1 .. T-2  (T-2 of them), ping-pong unrolled x2
    const int npairs = (T - 2) >> 1;
#pragma unroll 1
    for (int it = 0; it < npairs; it++) {
        STEP(1);
        STEP(0);
    }
    int finbuf = 1;
    if ((T - 2) & 1) { STEP(1); finbuf = 0; }

    // ---- epilogue: final matvec + x_{T-1}; reconstruct natural-log alpha.
    {
        float S0, S1;
        MATVEC_BODY(pbuf[w][finbuf]);
        const float m0 = (c0 == 0) ? NEG2 : 0.0f;
        const float o0 = (lg2f_(S0) + xq0.x * LOG2E + m0 + M) * LN2;
        const float o1 = (lg2f_(S1) + xq0.y * LOG2E +      M) * LN2;
        *(float2*)&out[(size_t)b * 64 + c0] = make_float2(o0, o1);
    }
}

extern "C" void kernel_launch(void* const* d_in, const int* in_sizes, int n_in,
                              void* d_out, int out_size)
{
    const float* X     = (const float*)d_in[0];
    const float* trans = (const float*)d_in[1];
    float* out = (float*)d_out;

    const int B = out_size / 64;               // 256
    const int T = in_sizes[0] / (B * 64);      // 512

    const int blocks = (B + 1) / 2;            // 2 warps per CTA, 1 batch each
    crf_forward_kernel<<<blocks, 64>>>(X, trans, out, B, T);
}